// round 1
// baseline (speedup 1.0000x reference)
#include <cuda_runtime.h>

// Problem: loss = alpha*mean(G) + (1-alpha)*mse
//   mse     = sum_{t>0} (t-p)^2 / max(count,1)
//   mean(G) = (1/N) * sum over 4 corners (3x3 each) of (t-p)*wr[i]*wr[j]
//             (double reflect-101 conv collapses; zero-sum kernel => interior
//              weights vanish; wr = [-0.75,-1,-0.25, 0...0, 0.25,1,0.75])

#define ALPHA 0.2
#define H_DIM 4096
#define W_DIM 4096

__device__ double g_sumsq;
__device__ double g_count;

__global__ void el_init_kernel() {
    g_sumsq = 0.0;
    g_count = 0.0;
}

__global__ void el_reduce_kernel(const float4* __restrict__ pred4,
                                 const float4* __restrict__ targ4,
                                 int n4) {
    float s = 0.0f;
    float c = 0.0f;
    int stride = gridDim.x * blockDim.x;
    for (int i = blockIdx.x * blockDim.x + threadIdx.x; i < n4; i += stride) {
        float4 t = __ldg(targ4 + i);
        float4 p = __ldg(pred4 + i);
        if (t.x > 0.0f) { float d = t.x - p.x; s = fmaf(d, d, s); c += 1.0f; }
        if (t.y > 0.0f) { float d = t.y - p.y; s = fmaf(d, d, s); c += 1.0f; }
        if (t.z > 0.0f) { float d = t.z - p.z; s = fmaf(d, d, s); c += 1.0f; }
        if (t.w > 0.0f) { float d = t.w - p.w; s = fmaf(d, d, s); c += 1.0f; }
    }

    // warp reduce
    #pragma unroll
    for (int o = 16; o > 0; o >>= 1) {
        s += __shfl_down_sync(0xFFFFFFFFu, s, o);
        c += __shfl_down_sync(0xFFFFFFFFu, c, o);
    }

    __shared__ float ss[8];
    __shared__ float sc[8];
    int lane = threadIdx.x & 31;
    int wid  = threadIdx.x >> 5;
    if (lane == 0) { ss[wid] = s; sc[wid] = c; }
    __syncthreads();

    if (wid == 0) {
        int nw = blockDim.x >> 5;
        s = (lane < nw) ? ss[lane] : 0.0f;
        c = (lane < nw) ? sc[lane] : 0.0f;
        #pragma unroll
        for (int o = 4; o > 0; o >>= 1) {
            s += __shfl_down_sync(0xFFFFFFFFu, s, o);
            c += __shfl_down_sync(0xFFFFFFFFu, c, o);
        }
        if (lane == 0) {
            atomicAdd(&g_sumsq, (double)s);
            atomicAdd(&g_count, (double)c);
        }
    }
}

__global__ void el_final_kernel(const float* __restrict__ pred,
                                const float* __restrict__ targ,
                                float* __restrict__ out) {
    // Boundary weights of the composed 5x5 zero-sum kernel under reflect-101.
    const int   idx[6] = {0, 1, 2, H_DIM - 3, H_DIM - 2, H_DIM - 1};
    const double w[6]  = {-0.75, -1.0, -0.25, 0.25, 1.0, 0.75};

    double corner = 0.0;
    #pragma unroll
    for (int a = 0; a < 6; a++) {
        #pragma unroll
        for (int b = 0; b < 6; b++) {
            long off = (long)idx[a] * W_DIM + idx[b];
            double d = (double)targ[off] - (double)pred[off];
            corner += d * w[a] * w[b];
        }
    }

    double cnt = g_count;
    if (cnt < 1.0) cnt = 1.0;
    double mse = g_sumsq / cnt;
    double N = (double)H_DIM * (double)W_DIM;
    double res = ALPHA * (corner / N) + (1.0 - ALPHA) * mse;
    out[0] = (float)res;
}

extern "C" void kernel_launch(void* const* d_in, const int* in_sizes, int n_in,
                              void* d_out, int out_size) {
    const float* pred = (const float*)d_in[0];
    const float* targ = (const float*)d_in[1];
    float* out = (float*)d_out;

    int n  = in_sizes[0];            // 4096*4096 = 16777216
    int n4 = n >> 2;                 // float4 count

    el_init_kernel<<<1, 1>>>();
    el_reduce_kernel<<<2048, 256>>>((const float4*)pred, (const float4*)targ, n4);
    el_final_kernel<<<1, 1>>>(pred, targ, out);
}